// round 6
// baseline (speedup 1.0000x reference)
#include <cuda_runtime.h>
#include <cuda_fp16.h>
#include <math_constants.h>

#define NPTS   8192
#define BATCH  4
#define KNN    4
#define QPB    224
#define SPLIT  4
#define THREADS (QPB * SPLIT)      // 896 threads = 28 warps
#define JPS    (NPTS / SPLIT)      // 2048 candidates per slice
#define G      16                  // candidates per fp16 filter group
#define GRPX   37                  // 37*4 = 148 blocks = 1 full wave
#define EPS    0.2f                // conservative fp16-filter error margin

#define PTS_BYTES  (NPTS * 16)                      // 131072 fp32 float4
#define HP_BYTES   ((NPTS / 2) * 16)                // 65536  packed half2 uint4
#define PART_N     (THREADS * KNN)                  // 3584
#define SMEM_BYTES (PTS_BYTES + HP_BYTES + PART_N * 8)   // 225280 B

__device__ __forceinline__ void insert4(float sv, int j,
                                        float& v0, float& v1, float& v2, float& v3,
                                        int& i0, int& i1, int& i2, int& i3) {
    if (sv > v3) {
        if (sv > v2) {
            v3 = v2; i3 = i2;
            if (sv > v1) {
                v2 = v1; i2 = i1;
                if (sv > v0) {
                    v1 = v0; i1 = i0;
                    v0 = sv; i0 = j;
                } else { v1 = sv; i1 = j; }
            } else { v2 = sv; i2 = j; }
        } else { v3 = sv; i3 = j; }
    }
}

__global__ __launch_bounds__(THREADS, 1)
void knn_gather_kernel(const float* __restrict__ x, float* __restrict__ out) {
    extern __shared__ char smem_raw[];
    float4* __restrict__ pts = (float4*)smem_raw;                              // [NPTS]
    uint4*  __restrict__ hp  = (uint4*)(smem_raw + PTS_BYTES);                 // [NPTS/2]
    float*  __restrict__ pv  = (float*)(smem_raw + PTS_BYTES + HP_BYTES);      // [PART_N]
    int*    __restrict__ pix = (int*)  (smem_raw + PTS_BYTES + HP_BYTES + PART_N*4);

    const int b = blockIdx.y;
    const float* __restrict__ xb = x + (size_t)b * NPTS * 3;

    // Stage fp32 points; h = 0.5*||p||^2 (s = <q,p> - h ranks like -||q-p||^2).
    for (int j = threadIdx.x; j < NPTS; j += THREADS) {
        float px = xb[3 * j + 0];
        float py = xb[3 * j + 1];
        float pz = xb[3 * j + 2];
        pts[j] = make_float4(px, py, pz, 0.5f * (px * px + py * py + pz * pz));
    }
    __syncthreads();

    // Build packed fp16 mirror: hp[j2] = {half2(x0,x1), half2(y0,y1), half2(z0,z1), half2(-h0,-h1)}
    for (int j2 = threadIdx.x; j2 < NPTS / 2; j2 += THREADS) {
        const float4 a = pts[2 * j2 + 0];
        const float4 c = pts[2 * j2 + 1];
        __half2 hx = __floats2half2_rn(a.x, c.x);
        __half2 hy = __floats2half2_rn(a.y, c.y);
        __half2 hz = __floats2half2_rn(a.z, c.z);
        __half2 nh = __floats2half2_rn(-a.w, -c.w);
        uint4 pk;
        pk.x = *(unsigned*)&hx;
        pk.y = *(unsigned*)&hy;
        pk.z = *(unsigned*)&hz;
        pk.w = *(unsigned*)&nh;
        hp[j2] = pk;
    }
    __syncthreads();

    const int t     = threadIdx.x;
    const int qi    = t % QPB;        // warps never straddle (224 = 7 warps)
    const int slice = t / QPB;
    const int q     = blockIdx.x * QPB + qi;
    const bool active = (q < NPTS);

    float v0 = -CUDART_INF_F, v1 = -CUDART_INF_F, v2 = -CUDART_INF_F, v3 = -CUDART_INF_F;
    int   i0 = 0, i1 = 0, i2 = 0, i3 = 0;

    if (active) {
        const float4 qp = pts[q];
        const float qx = qp.x, qy = qp.y, qz = qp.z;
        const __half2 qx2 = __float2half2_rn(qx);
        const __half2 qy2 = __float2half2_rn(qy);
        const __half2 qz2 = __float2half2_rn(qz);

        float thr = v3 - EPS;   // -inf
        const int jbase = slice * JPS;

        for (int j0 = jbase; j0 < jbase + JPS; j0 += G) {
            // fp16 packed filter: 16 candidates via 8 LDS.128 + 24 HFMA2 + 7 HMAX2
            __half2 m2;
            #pragma unroll
            for (int e = 0; e < G / 2; ++e) {
                const uint4 pk = hp[(j0 >> 1) + e];   // broadcast LDS.128
                const __half2 hx = *(const __half2*)&pk.x;
                const __half2 hy = *(const __half2*)&pk.y;
                const __half2 hz = *(const __half2*)&pk.z;
                const __half2 nh = *(const __half2*)&pk.w;
                const __half2 s2 = __hfma2(qx2, hx, __hfma2(qy2, hy, __hfma2(qz2, hz, nh)));
                m2 = (e == 0) ? s2 : __hmax2(m2, s2);
            }
            const float mm = __half2float(__hmax(__low2half(m2), __high2half(m2)));
            if (mm > thr) {
                // Exact fp32 verify + stable insert (identical math to R3 kernel)
                #pragma unroll
                for (int e = 0; e < G; ++e) {
                    const float4 p = pts[j0 + e];
                    float u = __fmaf_rn(qx, p.x, -p.w);
                    u       = __fmaf_rn(qy, p.y, u);
                    u       = __fmaf_rn(qz, p.z, u);
                    insert4(u, j0 + e, v0, v1, v2, v3, i0, i1, i2, i3);
                }
                thr = v3 - EPS;
            }
        }
        const int base = t * KNN;
        pv[base + 0] = v0; pix[base + 0] = i0;
        pv[base + 1] = v1; pix[base + 1] = i1;
        pv[base + 2] = v2; pix[base + 2] = i2;
        pv[base + 3] = v3; pix[base + 3] = i3;
    }
    __syncthreads();

    // Merge the 4 slice partials, slice-ascending = j-ascending => stable.
    if (active && slice == 0) {
        float w0 = -CUDART_INF_F, w1 = -CUDART_INF_F, w2 = -CUDART_INF_F, w3 = -CUDART_INF_F;
        int   k0 = 0, k1 = 0, k2 = 0, k3 = 0;
        #pragma unroll
        for (int sl = 0; sl < SPLIT; ++sl) {
            const int base = (sl * QPB + qi) * KNN;
            #pragma unroll
            for (int e = 0; e < KNN; ++e)
                insert4(pv[base + e], pix[base + e], w0, w1, w2, w3, k0, k1, k2, k3);
        }

        float* __restrict__ o = out + (((size_t)b * NPTS + q) * KNN) * 3;
        const float4 p0 = pts[k0];
        const float4 p1 = pts[k1];
        const float4 p2 = pts[k2];
        const float4 p3 = pts[k3];
        o[0]  = p0.x; o[1]  = p0.y; o[2]  = p0.z;
        o[3]  = p1.x; o[4]  = p1.y; o[5]  = p1.z;
        o[6]  = p2.x; o[7]  = p2.y; o[8]  = p2.z;
        o[9]  = p3.x; o[10] = p3.y; o[11] = p3.z;
    }
}

extern "C" void kernel_launch(void* const* d_in, const int* in_sizes, int n_in,
                              void* d_out, int out_size) {
    (void)n_in; (void)in_sizes; (void)out_size;
    const float* x = (const float*)d_in[0];
    float* out = (float*)d_out;

    cudaFuncSetAttribute(knn_gather_kernel,
                         cudaFuncAttributeMaxDynamicSharedMemorySize, SMEM_BYTES);

    dim3 grid(GRPX, BATCH, 1);   // 148 blocks = 1 wave
    dim3 block(THREADS, 1, 1);
    knn_gather_kernel<<<grid, block, SMEM_BYTES>>>(x, out);
}